// round 1
// baseline (speedup 1.0000x reference)
#include <cuda_runtime.h>
#include <stdint.h>

#define Bc   64
#define CIN  256
#define COUT 256
#define HW   28
#define NPIX (HW*HW)          // 784
#define NW   (COUT*CIN*9)     // 589824
#define KK   8

// scratch (no allocations allowed)
__device__ uint32_t g_wbits[COUT * 9 * 8];      // 18,432 words: [o][tap][cw]
__device__ uint32_t g_abits[Bc * NPIX * 8];     // 401,408 words: [b][y][x][cw]

// ---------------------------------------------------------------------------
// Kernel 1: binarized weights.  w[o,c,tap] = M + sum_k rv[k]*Z[k];
// bit = signbit(w)  (bit 1 <=> value -1). Pack over c via ballot.
// grid: <<<256, 256>>>  (o = blockIdx, c = threadIdx)
// ---------------------------------------------------------------------------
__global__ void wbits_kernel(const float* __restrict__ M,
                             const float* __restrict__ Z,
                             const float* __restrict__ rv)
{
    const int o    = blockIdx.x;
    const int c    = threadIdx.x;
    const int lane = c & 31;
    const int cw   = c >> 5;

    float rvl[KK];
#pragma unroll
    for (int k = 0; k < KK; k++) rvl[k] = __ldg(rv + k);

    const int base = (o * CIN + c) * 9;

    float wv[9];
#pragma unroll
    for (int j = 0; j < 9; j++) wv[j] = M[base + j];

#pragma unroll
    for (int k = 0; k < KK; k++) {
        const float* zp = Z + k * NW + base;
#pragma unroll
        for (int j = 0; j < 9; j++) wv[j] += rvl[k] * zp[j];
    }

#pragma unroll
    for (int j = 0; j < 9; j++) {
        unsigned bit  = __float_as_uint(wv[j]) >> 31;
        unsigned mask = __ballot_sync(0xffffffffu, bit);
        if (lane == 0) g_wbits[(o * 9 + j) * 8 + cw] = mask;
    }
}

// ---------------------------------------------------------------------------
// Kernel 2: binarize + bit-pack activations to [b][y][x][cw] layout.
// grid: <<<392, 128>>>  (392*128 = 64*28*28 exactly)
// ---------------------------------------------------------------------------
__global__ void abits_kernel(const float* __restrict__ x)
{
    const int pos = blockIdx.x * 128 + threadIdx.x;  // (b,y,x) flat
    const int xx  = pos % HW;
    const int y   = (pos / HW) % HW;
    const int b   = pos / NPIX;

    const float* xp = x + (long)b * CIN * NPIX + y * HW + xx;

    uint32_t w[8];
#pragma unroll
    for (int cw = 0; cw < 8; cw++) {
        uint32_t m = 0;
#pragma unroll
        for (int j = 0; j < 32; j++) {
            uint32_t s = __float_as_uint(xp[(cw * 32 + j) * NPIX]) >> 31;
            m |= s << j;
        }
        w[cw] = m;
    }

    uint4* dst = (uint4*)(g_abits + (long)pos * 8);
    dst[0] = make_uint4(w[0], w[1], w[2], w[3]);
    dst[1] = make_uint4(w[4], w[5], w[6], w[7]);
}

// ---------------------------------------------------------------------------
// Kernel 3: XNOR-popcount conv.
// block = (image b, group of 32 out-channels). 8 warps; lane = out-channel,
// warp handles rows y = warp, warp+8, ... All lanes of a warp share (y,x),
// so smem tap loads broadcast (conflict-free). Per-lane weights in registers.
// Output staged in padded smem, written back coalesced over x.
// grid: <<<512, 256, 54784>>>
// ---------------------------------------------------------------------------
__global__ void __launch_bounds__(256, 2)
conv_kernel(const float* __restrict__ alpha, float* __restrict__ out)
{
    extern __shared__ uint32_t sm[];          // [0,6272): image bits; then stage

    const int b   = blockIdx.x >> 3;
    const int og  = blockIdx.x & 7;
    const int tid = threadIdx.x;

    // cooperative image load (1568 uint4)
    {
        const uint4* src = (const uint4*)(g_abits + (long)b * NPIX * 8);
        uint4* d4 = (uint4*)sm;
        for (int i = tid; i < NPIX * 2; i += 256) d4[i] = src[i];
    }
    __syncthreads();

    const int lane = tid & 31;
    const int wrp  = tid >> 5;
    const int o    = og * 32 + lane;
    const float a  = alpha[o];

    uint32_t wr[9][8];
#pragma unroll
    for (int t = 0; t < 9; t++) {
        const uint4* wp = (const uint4*)(g_wbits + (o * 9 + t) * 8);
        uint4 q0 = wp[0], q1 = wp[1];
        wr[t][0] = q0.x; wr[t][1] = q0.y; wr[t][2] = q0.z; wr[t][3] = q0.w;
        wr[t][4] = q1.x; wr[t][5] = q1.y; wr[t][6] = q1.z; wr[t][7] = q1.w;
    }

    float* stage = (float*)(sm + NPIX * 8) + wrp * (32 * 29);  // pitch 29: bank-conflict-free

    for (int y = wrp; y < HW; y += 8) {
        const int rlo = (y > 0) ? 0 : 1;
        const int rhi = (y < HW - 1) ? 2 : 1;

        for (int x = 0; x < HW; x++) {
            const int clo = (x > 0) ? 0 : 1;
            const int chi = (x < HW - 1) ? 2 : 1;
            int mis = 0;
#pragma unroll
            for (int kh = 0; kh < 3; kh++) {
                if (kh < rlo || kh > rhi) continue;
                const int iy = y + kh - 1;
#pragma unroll
                for (int kw = 0; kw < 3; kw++) {
                    if (kw < clo || kw > chi) continue;
                    const int ix = x + kw - 1;
                    const uint4* p = (const uint4*)(sm + ((iy * HW + ix) << 3));
                    uint4 a0 = p[0], a1 = p[1];
                    const int t = kh * 3 + kw;
                    mis += __popc(a0.x ^ wr[t][0]);
                    mis += __popc(a0.y ^ wr[t][1]);
                    mis += __popc(a0.z ^ wr[t][2]);
                    mis += __popc(a0.w ^ wr[t][3]);
                    mis += __popc(a1.x ^ wr[t][4]);
                    mis += __popc(a1.y ^ wr[t][5]);
                    mis += __popc(a1.z ^ wr[t][6]);
                    mis += __popc(a1.w ^ wr[t][7]);
                }
            }
            const int vt = (rhi - rlo + 1) * (chi - clo + 1);   // valid taps
            stage[lane * 29 + x] = a * (float)(vt * 256 - 2 * mis);
        }
        __syncwarp();

        // coalesced writeback: lanes sweep x, loop over the 32 out-channels
        float* outb = out + ((long)(b * COUT + og * 32) * HW + y) * HW;
        if (lane < HW) {
#pragma unroll 4
            for (int oo = 0; oo < 32; oo++)
                outb[oo * NPIX + lane] = stage[oo * 29 + lane];
        }
        __syncwarp();
    }
}

// ---------------------------------------------------------------------------
extern "C" void kernel_launch(void* const* d_in, const int* in_sizes, int n_in,
                              void* d_out, int out_size)
{
    const float* x  = (const float*)d_in[0];
    const float* M  = (const float*)d_in[1];
    const float* Z  = (const float*)d_in[2];
    const float* al = (const float*)d_in[3];
    const float* rv = (const float*)d_in[4];

    cudaFuncSetAttribute(conv_kernel,
                         cudaFuncAttributeMaxDynamicSharedMemorySize, 56 * 1024);

    wbits_kernel<<<COUT, CIN>>>(M, Z, rv);
    abits_kernel<<<392, 128>>>(x);
    conv_kernel<<<Bc * 8, 256, (NPIX * 8) * 4 + 8 * 32 * 29 * 4>>>(al, (float*)d_out);
}